// round 1
// baseline (speedup 1.0000x reference)
#include <cuda_runtime.h>
#include <math.h>

// Problem constants (fixed shapes: B=8, C=256, H=128, W=128, heads=8, e=32)
#define MROWS 131072          // B*H*W... actually B*C*H*W/(W*C) * W rows = total rows of the flat (M,256) view
#define CDIM  256
#define NELEM (MROWS * CDIM)  // 33,554,432 floats = 128 MiB per buffer

// Scratch (allocation-free rule: __device__ globals)
__device__ float g_scale[NELEM];
__device__ float g_shift[NELEM];
__device__ float g_q[NELEM];
__device__ float g_k[NELEM];
__device__ float g_v[NELEM];
__device__ float g_attn[NELEM];

// ---------------------------------------------------------------------------
// SGEMM: out[m, n0..] = A[m, :] . W[n, :]   (y = A @ W^T), K = 256 fixed.
// BM=BN=128, BK=8, 256 threads, 8x8 microtile, double-buffered smem.
// Optional FiLM epilogue: out = scale * out + shift (same (m,n) indexing).
// ---------------------------------------------------------------------------
__global__ __launch_bounds__(256, 2)
void sgemm_k256(const float* __restrict__ A, const float* __restrict__ W,
                float* __restrict__ out,
                const float* __restrict__ scale, const float* __restrict__ shift)
{
    constexpr int K = 256, BM = 128, BN = 128, BK = 8;
    __shared__ float As[2][BK][BM];
    __shared__ float Bs[2][BK][BN];

    const int tid = threadIdx.x;
    const int m0 = blockIdx.y * BM;
    const int n0 = blockIdx.x * BN;

    // Global load mapping: each thread loads one float4 of A and one of W per k-tile.
    const int lm = tid >> 1;           // 0..127 (row within tile)
    const int lk = (tid & 1) << 2;     // 0 or 4 (col offset within BK)
    const float* ap = A + (size_t)(m0 + lm) * K + lk;
    const float* wp = W + (size_t)(n0 + lm) * K + lk;

    // Compute mapping: 16x16 thread grid, 8x8 outputs each.
    const int tx = tid & 15;   // n direction
    const int ty = tid >> 4;   // m direction

    float acc[8][8];
    #pragma unroll
    for (int i = 0; i < 8; i++)
        #pragma unroll
        for (int j = 0; j < 8; j++) acc[i][j] = 0.f;

    // Prologue: load tile 0
    float4 a4 = *(const float4*)ap;
    float4 b4 = *(const float4*)wp;
    As[0][lk + 0][lm] = a4.x; As[0][lk + 1][lm] = a4.y;
    As[0][lk + 2][lm] = a4.z; As[0][lk + 3][lm] = a4.w;
    Bs[0][lk + 0][lm] = b4.x; Bs[0][lk + 1][lm] = b4.y;
    Bs[0][lk + 2][lm] = b4.z; Bs[0][lk + 3][lm] = b4.w;
    __syncthreads();

    int buf = 0;
    #pragma unroll 1
    for (int kt = 0; kt < K / BK; kt++) {
        // Prefetch next tile into registers while computing current.
        if (kt + 1 < K / BK) {
            a4 = *(const float4*)(ap + (kt + 1) * BK);
            b4 = *(const float4*)(wp + (kt + 1) * BK);
        }
        #pragma unroll
        for (int kk = 0; kk < BK; kk++) {
            float ar[8], br[8];
            *(float4*)&ar[0] = *(const float4*)&As[buf][kk][ty * 8];
            *(float4*)&ar[4] = *(const float4*)&As[buf][kk][ty * 8 + 4];
            *(float4*)&br[0] = *(const float4*)&Bs[buf][kk][tx * 8];
            *(float4*)&br[4] = *(const float4*)&Bs[buf][kk][tx * 8 + 4];
            #pragma unroll
            for (int i = 0; i < 8; i++)
                #pragma unroll
                for (int j = 0; j < 8; j++)
                    acc[i][j] += ar[i] * br[j];
        }
        if (kt + 1 < K / BK) {
            buf ^= 1;
            As[buf][lk + 0][lm] = a4.x; As[buf][lk + 1][lm] = a4.y;
            As[buf][lk + 2][lm] = a4.z; As[buf][lk + 3][lm] = a4.w;
            Bs[buf][lk + 0][lm] = b4.x; Bs[buf][lk + 1][lm] = b4.y;
            Bs[buf][lk + 2][lm] = b4.z; Bs[buf][lk + 3][lm] = b4.w;
            __syncthreads();
        }
    }

    // Epilogue: optional FiLM modulation, vectorized store.
    const bool mod = (scale != nullptr);
    #pragma unroll
    for (int i = 0; i < 8; i++) {
        const size_t row = (size_t)(m0 + ty * 8 + i) * CDIM;
        #pragma unroll
        for (int jv = 0; jv < 2; jv++) {
            const int n = n0 + tx * 8 + jv * 4;
            float4 v;
            v.x = acc[i][jv * 4 + 0];
            v.y = acc[i][jv * 4 + 1];
            v.z = acc[i][jv * 4 + 2];
            v.w = acc[i][jv * 4 + 3];
            if (mod) {
                const float4 s = *(const float4*)(scale + row + n);
                const float4 t = *(const float4*)(shift + row + n);
                v.x = fmaf(s.x, v.x, t.x);
                v.y = fmaf(s.y, v.y, t.y);
                v.z = fmaf(s.z, v.z, t.z);
                v.w = fmaf(s.w, v.w, t.w);
            }
            *(float4*)(out + row + n) = v;
        }
    }
}

// ---------------------------------------------------------------------------
// Attention: one CTA per (batch, head). seq=128, e=32.
// K/V tiles in smem (warp-uniform reads -> broadcast, ~free).
// Score row per thread in smem, padded stride 129 -> conflict-free.
// ---------------------------------------------------------------------------
#define ATTN_SMEM (128 * 129 * 4 + 2 * 128 * 32 * 4)   // 98,816 B

__global__ __launch_bounds__(128)
void attn_kernel(const float* __restrict__ Q, const float* __restrict__ Kg,
                 const float* __restrict__ Vg, float* __restrict__ O)
{
    extern __shared__ float sm[];
    float*  S  = sm;                               // [128][129]
    float4* K4 = (float4*)(sm + 128 * 129);        // [128][8]
    float4* V4 = K4 + 128 * 8;                     // [128][8]

    const int bh = blockIdx.x;
    const int batch = bh >> 3;
    const int head  = bh & 7;
    const size_t r0 = (size_t)batch * 128;
    const int c0 = head * 32;
    const int tid = threadIdx.x;

    // Cooperative K/V tile load (coalesced float4)
    for (int idx = tid; idx < 1024; idx += 128) {
        const int j = idx >> 3, e4 = idx & 7;
        K4[idx] = *(const float4*)(Kg + (r0 + j) * CDIM + c0 + e4 * 4);
        V4[idx] = *(const float4*)(Vg + (r0 + j) * CDIM + c0 + e4 * 4);
    }
    // This thread's query row in registers
    float4 q[8];
    #pragma unroll
    for (int e4 = 0; e4 < 8; e4++)
        q[e4] = *(const float4*)(Q + (r0 + tid) * CDIM + c0 + e4 * 4);
    __syncthreads();

    const float sc = 0.17677669529663687f;  // 1/sqrt(32)
    float* Srow = S + tid * 129;

    // Scores + running max (4 independent FMA chains to avoid serial dependency)
    float mx = -1e30f;
    #pragma unroll 4
    for (int j = 0; j < 128; j++) {
        float d0 = 0.f, d1 = 0.f, d2 = 0.f, d3 = 0.f;
        #pragma unroll
        for (int e4 = 0; e4 < 8; e4++) {
            const float4 kv = K4[j * 8 + e4];
            d0 = fmaf(q[e4].x, kv.x, d0);
            d1 = fmaf(q[e4].y, kv.y, d1);
            d2 = fmaf(q[e4].z, kv.z, d2);
            d3 = fmaf(q[e4].w, kv.w, d3);
        }
        const float d = ((d0 + d1) + (d2 + d3)) * sc;
        Srow[j] = d;
        mx = fmaxf(mx, d);
    }

    // Softmax (unnormalized in smem; fold 1/sum into PV epilogue)
    float sum = 0.f;
    #pragma unroll 4
    for (int j = 0; j < 128; j++) {
        const float p = __expf(Srow[j] - mx);
        Srow[j] = p;
        sum += p;
    }
    const float inv = 1.f / sum;

    // PV
    float4 acc[8];
    #pragma unroll
    for (int e4 = 0; e4 < 8; e4++) acc[e4] = make_float4(0.f, 0.f, 0.f, 0.f);
    #pragma unroll 2
    for (int j = 0; j < 128; j++) {
        const float p = Srow[j];
        #pragma unroll
        for (int e4 = 0; e4 < 8; e4++) {
            const float4 v = V4[j * 8 + e4];
            acc[e4].x = fmaf(p, v.x, acc[e4].x);
            acc[e4].y = fmaf(p, v.y, acc[e4].y);
            acc[e4].z = fmaf(p, v.z, acc[e4].z);
            acc[e4].w = fmaf(p, v.w, acc[e4].w);
        }
    }
    #pragma unroll
    for (int e4 = 0; e4 < 8; e4++) {
        float4 r;
        r.x = acc[e4].x * inv; r.y = acc[e4].y * inv;
        r.z = acc[e4].z * inv; r.w = acc[e4].w * inv;
        *(float4*)(O + (r0 + tid) * CDIM + c0 + e4 * 4) = r;
    }
}

// ---------------------------------------------------------------------------
// Launch: 5 projection GEMMs (scale/shift plain; q/k/v FiLM-fused epilogue),
// attention, output GEMM. All on the capture stream, no syncs, no allocs.
// ---------------------------------------------------------------------------
extern "C" void kernel_launch(void* const* d_in, const int* in_sizes, int n_in,
                              void* d_out, int out_size)
{
    const float* x      = (const float*)d_in[0];
    const float* ctx    = (const float*)d_in[1];
    const float* Wq     = (const float*)d_in[2];
    const float* Wkv    = (const float*)d_in[3];
    const float* Wout   = (const float*)d_in[4];
    const float* Wscale = (const float*)d_in[5];
    const float* Wshift = (const float*)d_in[6];
    float* out = (float*)d_out;

    float *gs, *gt, *gq, *gk, *gv, *ga;
    cudaGetSymbolAddress((void**)&gs, g_scale);
    cudaGetSymbolAddress((void**)&gt, g_shift);
    cudaGetSymbolAddress((void**)&gq, g_q);
    cudaGetSymbolAddress((void**)&gk, g_k);
    cudaGetSymbolAddress((void**)&gv, g_v);
    cudaGetSymbolAddress((void**)&ga, g_attn);

    cudaFuncSetAttribute(attn_kernel,
                         cudaFuncAttributeMaxDynamicSharedMemorySize, ATTN_SMEM);

    const dim3 ggrid(CDIM / 128, MROWS / 128);  // (2, 1024)
    const dim3 gblk(256);

    // scale/shift first (needed by the q/k/v epilogues)
    sgemm_k256<<<ggrid, gblk>>>(ctx, Wscale, gs, nullptr, nullptr);
    sgemm_k256<<<ggrid, gblk>>>(ctx, Wshift, gt, nullptr, nullptr);

    // q/k/v with FiLM modulation fused into the epilogue
    sgemm_k256<<<ggrid, gblk>>>(x, Wq,                gq, gs, gt);
    sgemm_k256<<<ggrid, gblk>>>(x, Wkv,               gk, gs, gt);  // k = Wkv rows [0,256)
    sgemm_k256<<<ggrid, gblk>>>(x, Wkv + 256 * CDIM,  gv, gs, gt);  // v = Wkv rows [256,512)

    // attention: 1024 batches x 8 heads
    attn_kernel<<<8192, 128, ATTN_SMEM>>>(gq, gk, gv, ga);

    // output projection straight into d_out
    sgemm_k256<<<ggrid, gblk>>>(ga, Wout, out, nullptr, nullptr);
}

// round 5
// speedup vs baseline: 2.1220x; 2.1220x over previous
#include <cuda_runtime.h>
#include <cuda_fp16.h>
#include <cstdint>
#include <math.h>

// Fixed shapes: B=8, C=256, H=128, W=128, heads=8, e=32
#define MROWS 131072
#define CDIM  256
#define NELEM (MROWS * CDIM)

// Scratch (allocation-free rule: __device__ globals)
__device__ float g_scale[NELEM];
__device__ float g_shift[NELEM];
__device__ float g_q[NELEM];
__device__ float g_k[NELEM];
__device__ float g_v[NELEM];
__device__ float g_attn[NELEM];

// ---------------------------------------------------------------------------
// PTX helpers (sm_80-level: ldmatrix + mma.sync only, no tcgen05)
// ---------------------------------------------------------------------------
__device__ __forceinline__ uint32_t smem_u32(const void* p) {
    uint32_t a;
    asm("{ .reg .u64 t; cvta.to.shared.u64 t, %1; cvt.u32.u64 %0, t; }"
        : "=r"(a) : "l"(p));
    return a;
}

#define LDSM_X4(r0, r1, r2, r3, addr)                                         \
    asm volatile("ldmatrix.sync.aligned.m8n8.x4.shared.b16 {%0,%1,%2,%3}, [%4];" \
                 : "=r"(r0), "=r"(r1), "=r"(r2), "=r"(r3) : "r"(addr))

#define MMA16816(d, a, b0, b1)                                                \
    asm volatile("mma.sync.aligned.m16n8k16.row.col.f32.f16.f16.f32 "         \
                 "{%0,%1,%2,%3}, {%4,%5,%6,%7}, {%8,%9}, {%0,%1,%2,%3};"      \
                 : "+f"((d)[0]), "+f"((d)[1]), "+f"((d)[2]), "+f"((d)[3])     \
                 : "r"((a)[0]), "r"((a)[1]), "r"((a)[2]), "r"((a)[3]),        \
                   "r"(b0), "r"(b1))

__device__ __forceinline__ uint32_t packh2(float x, float y) {
    __half2 h = __floats2half2_rn(x, y);   // low half = x (lower address)
    return *(uint32_t*)&h;
}

// Swizzled smem byte offset for chunk (row, c) of a [128][32]-fp16 tile
// stored as 64 pair-rows x 128B. row in [0,128), c in [0,4) (16B chunks).
__device__ __forceinline__ uint32_t tile_off(int row, int c) {
    const int pr = row >> 1;
    const int ch = ((row & 1) << 2) | c;
    return (uint32_t)(pr * 128 + ((ch ^ (pr & 7)) << 4));
}

// ---------------------------------------------------------------------------
// fp16 tensor-core GEMM: out[m,n] = sum_k A[m,k]*W[n,k], K=256, fp32 accum.
// CTA 128x128, 256 threads (8 warps, 4x2), BK=32, double-buffered smem,
// fp32->fp16 convert on the load path, fused FiLM epilogue.
// ---------------------------------------------------------------------------
__global__ void __launch_bounds__(256)
gemm_h16(const float* __restrict__ A, const float* __restrict__ W,
         float* __restrict__ out,
         const float* __restrict__ scale, const float* __restrict__ shift)
{
    constexpr int K = 256;
    __shared__ alignas(128) uint8_t sA[2][8192];   // [128][32] fp16, swizzled
    __shared__ alignas(128) uint8_t sB[2][8192];

    const int tid  = threadIdx.x;
    const int wid  = tid >> 5;
    const int lane = tid & 31;
    const int m0 = blockIdx.y * 128;
    const int n0 = blockIdx.x * 128;

    const int warp_m = (wid & 3) * 32;   // 4 warps down M
    const int warp_n = (wid >> 2) * 64;  // 2 warps across N

    const uint32_t sa0 = smem_u32(&sA[0][0]);
    const uint32_t sa1 = smem_u32(&sA[1][0]);
    const uint32_t sb0 = smem_u32(&sB[0][0]);
    const uint32_t sb1 = smem_u32(&sB[1][0]);

    // Loader mapping: idx -> (row = idx>>2, chunk c = idx&3); idx = tid, tid+256.
    const int r0i = tid >> 2, c0i = tid & 3;
    const int r1i = (tid + 256) >> 2, c1i = tid & 3;
    const float* Ap = A + (size_t)m0 * K;
    const float* Wp = W + (size_t)n0 * K;

    float d[2][8][4];
    #pragma unroll
    for (int mt = 0; mt < 2; mt++)
        #pragma unroll
        for (int nt = 0; nt < 8; nt++)
            #pragma unroll
            for (int i = 0; i < 4; i++) d[mt][nt][i] = 0.f;

    uint4 pa[2], pb[2];

    // gmem load of one (row, chunk) = 8 floats -> 8 fp16 (uint4)
    auto ldcvt = [&](const float* base, int row, int c, int kt) -> uint4 {
        const float4* p = (const float4*)(base + (size_t)row * K + kt * 32 + c * 8);
        const float4 f0 = p[0], f1 = p[1];
        uint4 u;
        u.x = packh2(f0.x, f0.y); u.y = packh2(f0.z, f0.w);
        u.z = packh2(f1.x, f1.y); u.w = packh2(f1.z, f1.w);
        return u;
    };
    auto store_stage = [&](uint32_t abuf, uint32_t bbuf) {
        asm volatile("st.shared.v4.b32 [%0], {%1,%2,%3,%4};" ::
            "r"(abuf + tile_off(r0i, c0i)), "r"(pa[0].x), "r"(pa[0].y), "r"(pa[0].z), "r"(pa[0].w) : "memory");
        asm volatile("st.shared.v4.b32 [%0], {%1,%2,%3,%4};" ::
            "r"(abuf + tile_off(r1i, c1i)), "r"(pa[1].x), "r"(pa[1].y), "r"(pa[1].z), "r"(pa[1].w) : "memory");
        asm volatile("st.shared.v4.b32 [%0], {%1,%2,%3,%4};" ::
            "r"(bbuf + tile_off(r0i, c0i)), "r"(pb[0].x), "r"(pb[0].y), "r"(pb[0].z), "r"(pb[0].w) : "memory");
        asm volatile("st.shared.v4.b32 [%0], {%1,%2,%3,%4};" ::
            "r"(bbuf + tile_off(r1i, c1i)), "r"(pb[1].x), "r"(pb[1].y), "r"(pb[1].z), "r"(pb[1].w) : "memory");
    };

    // Prologue: stage 0
    pa[0] = ldcvt(Ap, r0i, c0i, 0); pa[1] = ldcvt(Ap, r1i, c1i, 0);
    pb[0] = ldcvt(Wp, r0i, c0i, 0); pb[1] = ldcvt(Wp, r1i, c1i, 0);
    store_stage(sa0, sb0);
    __syncthreads();

    #pragma unroll 1
    for (int kt = 0; kt < 8; kt++) {
        // Prefetch next stage from gmem (overlaps with mma below)
        if (kt < 7) {
            pa[0] = ldcvt(Ap, r0i, c0i, kt + 1); pa[1] = ldcvt(Ap, r1i, c1i, kt + 1);
            pb[0] = ldcvt(Wp, r0i, c0i, kt + 1); pb[1] = ldcvt(Wp, r1i, c1i, kt + 1);
        }
        const uint32_t abuf = (kt & 1) ? sa1 : sa0;
        const uint32_t bbuf = (kt & 1) ? sb1 : sb0;

        #pragma unroll
        for (int s = 0; s < 2; s++) {           // two k16 steps per stage
            uint32_t a[2][4];
            #pragma unroll
            for (int mt = 0; mt < 2; mt++) {
                const int R = warp_m + mt * 16 + (lane & 15);
                const int c = s * 2 + (lane >> 4);
                LDSM_X4(a[mt][0], a[mt][1], a[mt][2], a[mt][3],
                        abuf + tile_off(R, c));
            }
            #pragma unroll
            for (int np = 0; np < 4; np++) {    // each x4 covers two n8 tiles
                const int g = lane >> 3, lr = lane & 7;
                const int Rn = warp_n + np * 16 + ((g >> 1) << 3) + lr;
                const int c = s * 2 + (g & 1);
                uint32_t b[4];
                LDSM_X4(b[0], b[1], b[2], b[3], bbuf + tile_off(Rn, c));
                #pragma unroll
                for (int mt = 0; mt < 2; mt++) {
                    MMA16816(d[mt][np * 2 + 0], a[mt], b[0], b[1]);
                    MMA16816(d[mt][np * 2 + 1], a[mt], b[2], b[3]);
                }
            }
        }
        __syncthreads();
        if (kt < 7) {
            store_stage((kt & 1) ? sa0 : sa1, (kt & 1) ? sb0 : sb1);
            __syncthreads();
        }
    }

    // Epilogue: d[mt][nt]: rows m0+warp_m+mt*16+(lane>>2)(+8), cols n0+warp_n+nt*8+2*(lane&3)
    const bool mod = (scale != nullptr);
    #pragma unroll
    for (int mt = 0; mt < 2; mt++) {
        #pragma unroll
        for (int half = 0; half < 2; half++) {
            const int row = m0 + warp_m + mt * 16 + (lane >> 2) + half * 8;
            const size_t rbase = (size_t)row * CDIM;
            #pragma unroll
            for (int nt = 0; nt < 8; nt++) {
                const int col = n0 + warp_n + nt * 8 + (lane & 3) * 2;
                float2 v;
                v.x = d[mt][nt][half * 2 + 0];
                v.y = d[mt][nt][half * 2 + 1];
                if (mod) {
                    const float2 s = *(const float2*)(scale + rbase + col);
                    const float2 t = *(const float2*)(shift + rbase + col);
                    v.x = fmaf(s.x, v.x, t.x);
                    v.y = fmaf(s.y, v.y, t.y);
                }
                *(float2*)(out + rbase + col) = v;
            }
        }
    }
}

// ---------------------------------------------------------------------------
// Attention (unchanged from R1): one CTA per (batch, head). seq=128, e=32.
// ---------------------------------------------------------------------------
#define ATTN_SMEM (128 * 129 * 4 + 2 * 128 * 32 * 4)

__global__ void __launch_bounds__(128)
attn_kernel(const float* __restrict__ Q, const float* __restrict__ Kg,
            const float* __restrict__ Vg, float* __restrict__ O)
{
    extern __shared__ float sm[];
    float*  S  = sm;                               // [128][129]
    float4* K4 = (float4*)(sm + 128 * 129);        // [128][8]
    float4* V4 = K4 + 128 * 8;                     // [128][8]

    const int bh = blockIdx.x;
    const int batch = bh >> 3;
    const int head  = bh & 7;
    const size_t r0 = (size_t)batch * 128;
    const int c0 = head * 32;
    const int tid = threadIdx.x;

    for (int idx = tid; idx < 1024; idx += 128) {
        const int j = idx >> 3, e4 = idx & 7;
        K4[idx] = *(const float4*)(Kg + (r0 + j) * CDIM + c0 + e4 * 4);
        V4[idx] = *(const float4*)(Vg + (r0 + j) * CDIM + c0 + e4 * 4);
    }
    float4 q[8];
    #pragma unroll
    for (int e4 = 0; e4 < 8; e4++)
        q[e4] = *(const float4*)(Q + (r0 + tid) * CDIM + c0 + e4 * 4);
    __syncthreads();

    const float sc = 0.17677669529663687f;
    float* Srow = S + tid * 129;

    float mx = -1e30f;
    #pragma unroll 4
    for (int j = 0; j < 128; j++) {
        float d0 = 0.f, d1 = 0.f, d2 = 0.f, d3 = 0.f;
        #pragma unroll
        for (int e4 = 0; e4 < 8; e4++) {
            const float4 kv = K4[j * 8 + e4];
            d0 = fmaf(q[e4].x, kv.x, d0);
            d1 = fmaf(q[e4].y, kv.y, d1);
            d2 = fmaf(q[e4].z, kv.z, d2);
            d3 = fmaf(q[e4].w, kv.w, d3);
        }
        const float d = ((d0 + d1) + (d2 + d3)) * sc;
        Srow[j] = d;
        mx = fmaxf(mx, d);
    }

    float sum = 0.f;
    #pragma unroll 4
    for (int j = 0; j < 128; j++) {
        const float p = __expf(Srow[j] - mx);
        Srow[j] = p;
        sum += p;
    }
    const float inv = 1.f / sum;

    float4 acc[8];
    #pragma unroll
    for (int e4 = 0; e4 < 8; e4++) acc[e4] = make_float4(0.f, 0.f, 0.f, 0.f);
    #pragma unroll 2
    for (int j = 0; j < 128; j++) {
        const float p = Srow[j];
        #pragma unroll
        for (int e4 = 0; e4 < 8; e4++) {
            const float4 v = V4[j * 8 + e4];
            acc[e4].x = fmaf(p, v.x, acc[e4].x);
            acc[e4].y = fmaf(p, v.y, acc[e4].y);
            acc[e4].z = fmaf(p, v.z, acc[e4].z);
            acc[e4].w = fmaf(p, v.w, acc[e4].w);
        }
    }
    #pragma unroll
    for (int e4 = 0; e4 < 8; e4++) {
        float4 r;
        r.x = acc[e4].x * inv; r.y = acc[e4].y * inv;
        r.z = acc[e4].z * inv; r.w = acc[e4].w * inv;
        *(float4*)(O + (r0 + tid) * CDIM + c0 + e4 * 4) = r;
    }
}

// ---------------------------------------------------------------------------
// Launch
// ---------------------------------------------------------------------------
extern "C" void kernel_launch(void* const* d_in, const int* in_sizes, int n_in,
                              void* d_out, int out_size)
{
    const float* x      = (const float*)d_in[0];
    const float* ctx    = (const float*)d_in[1];
    const float* Wq     = (const float*)d_in[2];
    const float* Wkv    = (const float*)d_in[3];
    const float* Wout   = (const float*)d_in[4];
    const float* Wscale = (const float*)d_in[5];
    const float* Wshift = (const float*)d_in[6];
    float* out = (float*)d_out;

    float *gs, *gt, *gq, *gk, *gv, *ga;
    cudaGetSymbolAddress((void**)&gs, g_scale);
    cudaGetSymbolAddress((void**)&gt, g_shift);
    cudaGetSymbolAddress((void**)&gq, g_q);
    cudaGetSymbolAddress((void**)&gk, g_k);
    cudaGetSymbolAddress((void**)&gv, g_v);
    cudaGetSymbolAddress((void**)&ga, g_attn);

    cudaFuncSetAttribute(attn_kernel,
                         cudaFuncAttributeMaxDynamicSharedMemorySize, ATTN_SMEM);

    const dim3 ggrid(2, 1024);   // (N/128, M/128)
    const dim3 gblk(256);

    gemm_h16<<<ggrid, gblk>>>(ctx, Wscale, gs, nullptr, nullptr);
    gemm_h16<<<ggrid, gblk>>>(ctx, Wshift, gt, nullptr, nullptr);
    gemm_h16<<<ggrid, gblk>>>(x, Wq,               gq, gs, gt);
    gemm_h16<<<ggrid, gblk>>>(x, Wkv,              gk, gs, gt);
    gemm_h16<<<ggrid, gblk>>>(x, Wkv + 256 * CDIM, gv, gs, gt);

    attn_kernel<<<8192, 128, ATTN_SMEM>>>(gq, gk, gv, ga);

    gemm_h16<<<ggrid, gblk>>>(ga, Wout, out, nullptr, nullptr);
}